// round 5
// baseline (speedup 1.0000x reference)
#include <cuda_runtime.h>
#include <math.h>

#define BB 32
#define SS 2048
#define DD 1024
#define ROWS 16
#define CHUNKS (SS / ROWS)      // 128 blocks per batch
#define NBLK (BB * CHUNKS)      // 4096 blocks total
#define BETA_F 0.1f
#define RHO_F 1.0f

// Deterministic per-block partials (no float atomics -> bitwise stable across replays)
__device__ float g_p1[NBLK];
__device__ float g_p2[NBLK];
__device__ unsigned int g_count = 0;   // last-block ticket; self-resets each launch

__global__ void __launch_bounds__(256) wdpo_fused(const float* __restrict__ e1,
                                                  const float* __restrict__ e2,
                                                  const float* __restrict__ w,
                                                  const float* __restrict__ lp1ref,
                                                  const float* __restrict__ lp2ref,
                                                  const float* __restrict__ pref,
                                                  float* __restrict__ out) {
    const int t   = threadIdx.x;            // 0..255, owns a float4 column group
    const int blk = blockIdx.x;
    const int b     = blk >> 7;             // / CHUNKS
    const int chunk = blk & (CHUNKS - 1);
    const int lane = t & 31, wid = t >> 5;

    // each thread keeps its 4 w values in registers for the whole block
    const float4 w4 = reinterpret_cast<const float4*>(w)[t];

    const size_t base = ((size_t)b * SS + (size_t)chunk * ROWS) * DD + 4 * (size_t)t;
    const float4* __restrict__ p1 = reinterpret_cast<const float4*>(e1 + base);
    const float4* __restrict__ p2 = reinterpret_cast<const float4*>(e2 + base);

    // streaming loads (touched once — evict-first), 2 accumulators per stream for ILP
    float s1a = 0.f, s1b = 0.f, s2a = 0.f, s2b = 0.f;
#pragma unroll
    for (int r = 0; r < ROWS; r += 2) {
        const float4 a0 = __ldcs(&p1[(size_t)(r    ) * (DD / 4)]);
        const float4 a1 = __ldcs(&p1[(size_t)(r + 1) * (DD / 4)]);
        const float4 c0 = __ldcs(&p2[(size_t)(r    ) * (DD / 4)]);
        const float4 c1 = __ldcs(&p2[(size_t)(r + 1) * (DD / 4)]);
        s1a += a0.x * w4.x + a0.y * w4.y + a0.z * w4.z + a0.w * w4.w;
        s1b += a1.x * w4.x + a1.y * w4.y + a1.z * w4.z + a1.w * w4.w;
        s2a += c0.x * w4.x + c0.y * w4.y + c0.z * w4.z + c0.w * w4.w;
        s2b += c1.x * w4.x + c1.y * w4.y + c1.z * w4.z + c1.w * w4.w;
    }
    float s1 = s1a + s1b, s2 = s2a + s2b;

    // block reduction: warp shuffle then 8-warp shared fold
    __shared__ float sh1[8], sh2[8];
#pragma unroll
    for (int o = 16; o; o >>= 1) {
        s1 += __shfl_down_sync(0xffffffffu, s1, o);
        s2 += __shfl_down_sync(0xffffffffu, s2, o);
    }
    if (lane == 0) { sh1[wid] = s1; sh2[wid] = s2; }
    __syncthreads();
    if (wid == 0) {
        s1 = (lane < 8) ? sh1[lane] : 0.f;
        s2 = (lane < 8) ? sh2[lane] : 0.f;
#pragma unroll
        for (int o = 4; o; o >>= 1) {
            s1 += __shfl_down_sync(0xffffffffu, s1, o);
            s2 += __shfl_down_sync(0xffffffffu, s2, o);
        }
        if (lane == 0) { g_p1[blk] = s1; g_p2[blk] = s2; }
    }

    // ---- last-block-done epilogue (fused; removes the 5.5us tail kernel) ----
    __shared__ int s_last;
    __threadfence();                         // partials visible device-wide
    if (t == 0) {
        unsigned int prev = atomicAdd(&g_count, 1u);
        s_last = (prev == NBLK - 1u) ? 1 : 0;
    }
    __syncthreads();
    if (!s_last) return;

    // This block is last: fold all partials + scalar epilogue.
    __shared__ float s_ind[BB];
    __shared__ float s_gns[BB];
    __shared__ float s_wsq;

    // ||w||^2 : this block's w4 registers cover all of D
    {
        float v = w4.x * w4.x + w4.y * w4.y + w4.z * w4.z + w4.w * w4.w;
#pragma unroll
        for (int o = 16; o; o >>= 1) v += __shfl_down_sync(0xffffffffu, v, o);
        if (lane == 0) sh1[wid] = v;         // reuse sh1
        __syncthreads();
        if (t == 0) {
            float a = 0.f;
#pragma unroll
            for (int i = 0; i < 8; i++) a += sh1[i];
            s_wsq = a;
        }
        __syncthreads();
    }
    const float wsq = s_wsq;

    // warp `wid` folds batches wid*4 .. wid*4+3 (fixed order -> deterministic)
#pragma unroll
    for (int j = 0; j < 4; j++) {
        const int bb = wid * 4 + j;
        const int pb = bb * CHUNKS;
        float a1 = __ldcg(&g_p1[pb + lane])       + __ldcg(&g_p1[pb + lane + 32]) +
                   __ldcg(&g_p1[pb + lane + 64])  + __ldcg(&g_p1[pb + lane + 96]);
        float a2 = __ldcg(&g_p2[pb + lane])       + __ldcg(&g_p2[pb + lane + 32]) +
                   __ldcg(&g_p2[pb + lane + 64])  + __ldcg(&g_p2[pb + lane + 96]);
#pragma unroll
        for (int o = 16; o; o >>= 1) {
            a1 += __shfl_down_sync(0xffffffffu, a1, o);
            a2 += __shfl_down_sync(0xffffffffu, a2, o);
        }
        if (lane == 0) {
            const float h = (a1 - lp1ref[bb]) - (a2 - lp2ref[bb]);
            const float z = BETA_F * h;
            const float p = pref[bb];
            // stable softplus: softplus(x) = max(x,0) + log1p(exp(-|x|))
            const float lp = log1pf(expf(-fabsf(z)));
            const float sp_pos = fmaxf(z, 0.f) + lp;   // softplus(z)  = l2
            const float sp_neg = fmaxf(-z, 0.f) + lp;  // softplus(-z) = l1
            const float ind = p * sp_neg + (1.f - p) * sp_pos;
            const float sig = 1.f / (1.f + expf(-z));
            const float c = BETA_F * (sig - p);
            s_ind[bb] = ind;
            s_gns[bb] = 2.f * (float)SS * wsq * c * c;
        }
    }
    __syncthreads();
    if (wid == 0) {
        float i = s_ind[lane];
        float g = s_gns[lane];
#pragma unroll
        for (int o = 16; o; o >>= 1) {
            i += __shfl_down_sync(0xffffffffu, i, o);
            g += __shfl_down_sync(0xffffffffu, g, o);
        }
        if (lane == 0) {
            out[0] = i * (1.f / (float)BB) + RHO_F * sqrtf(g * (1.f / (float)BB));
            g_count = 0;                     // reset ticket for next graph replay
        }
    }
}

extern "C" void kernel_launch(void* const* d_in, const int* in_sizes, int n_in,
                              void* d_out, int out_size) {
    const float* e1     = (const float*)d_in[0];  // emb_a1 (B,S,D)
    const float* e2     = (const float*)d_in[1];  // emb_a2 (B,S,D)
    const float* w      = (const float*)d_in[2];  // w (D,)
    const float* lp1ref = (const float*)d_in[3];  // log_prob_a1_ref (B,)
    const float* lp2ref = (const float*)d_in[4];  // log_prob_a2_ref (B,)
    const float* pref   = (const float*)d_in[5];  // preference (B,)
    float* out          = (float*)d_out;

    wdpo_fused<<<NBLK, 256>>>(e1, e2, w, lp1ref, lp2ref, pref, out);
}

// round 6
// speedup vs baseline: 1.0305x; 1.0305x over previous
#include <cuda_runtime.h>
#include <math.h>

#define BB 32
#define SS 2048
#define DD 1024
#define ROWS 16
#define CHUNKS (SS / ROWS)      // 128 blocks per batch
#define NBLK (BB * CHUNKS)      // 4096 blocks total
#define BETA_F 0.1f
#define RHO_F 1.0f

// Deterministic per-block partials (no float atomics -> bitwise stable across replays)
__device__ float g_p1[NBLK];
__device__ float g_p2[NBLK];
__device__ unsigned int g_count = 0;   // last-block ticket; self-resets each launch

// __launch_bounds__(256, 8): cap regs at 32 so 8 CTAs/SM (100% occ). The
// epilogue path may spill — it runs in ONE block, once; the streaming loop
// (4096 blocks) gets full latency-hiding occupancy.
__global__ void __launch_bounds__(256, 8) wdpo_fused(const float* __restrict__ e1,
                                                     const float* __restrict__ e2,
                                                     const float* __restrict__ w,
                                                     const float* __restrict__ lp1ref,
                                                     const float* __restrict__ lp2ref,
                                                     const float* __restrict__ pref,
                                                     float* __restrict__ out) {
    const int t   = threadIdx.x;            // 0..255, owns a float4 column group
    const int blk = blockIdx.x;
    const int b     = blk >> 7;             // / CHUNKS
    const int chunk = blk & (CHUNKS - 1);
    const int lane = t & 31, wid = t >> 5;

    // each thread keeps its 4 w values in registers for the whole block
    const float4 w4 = reinterpret_cast<const float4*>(w)[t];

    const size_t base = ((size_t)b * SS + (size_t)chunk * ROWS) * DD + 4 * (size_t)t;
    const float4* __restrict__ p1 = reinterpret_cast<const float4*>(e1 + base);
    const float4* __restrict__ p2 = reinterpret_cast<const float4*>(e2 + base);

    // R3 loop body verbatim — measured 6.97 TB/s at full occupancy
    float s1 = 0.f, s2 = 0.f;
#pragma unroll 8
    for (int r = 0; r < ROWS; r++) {
        const float4 a = p1[(size_t)r * (DD / 4)];
        const float4 c = p2[(size_t)r * (DD / 4)];
        s1 += a.x * w4.x + a.y * w4.y + a.z * w4.z + a.w * w4.w;
        s2 += c.x * w4.x + c.y * w4.y + c.z * w4.z + c.w * w4.w;
    }

    // block reduction: warp shuffle then 8-warp shared fold
    __shared__ float sh1[8], sh2[8];
#pragma unroll
    for (int o = 16; o; o >>= 1) {
        s1 += __shfl_down_sync(0xffffffffu, s1, o);
        s2 += __shfl_down_sync(0xffffffffu, s2, o);
    }
    if (lane == 0) { sh1[wid] = s1; sh2[wid] = s2; }
    __syncthreads();
    if (wid == 0) {
        s1 = (lane < 8) ? sh1[lane] : 0.f;
        s2 = (lane < 8) ? sh2[lane] : 0.f;
#pragma unroll
        for (int o = 4; o; o >>= 1) {
            s1 += __shfl_down_sync(0xffffffffu, s1, o);
            s2 += __shfl_down_sync(0xffffffffu, s2, o);
        }
        if (lane == 0) { g_p1[blk] = s1; g_p2[blk] = s2; }
    }

    // ---- last-block-done epilogue (removes the 5.5us tail kernel) ----
    __shared__ int s_last;
    __threadfence();                         // partials visible device-wide
    if (t == 0) {
        unsigned int prev = atomicAdd(&g_count, 1u);
        s_last = (prev == NBLK - 1u) ? 1 : 0;
    }
    __syncthreads();
    if (!s_last) return;

    // This block is last: fold all partials + scalar epilogue.
    __shared__ float s_ind[BB];
    __shared__ float s_gns[BB];
    __shared__ float s_wsq;

    // ||w||^2 : this block's w4 registers cover all of D
    {
        float v = w4.x * w4.x + w4.y * w4.y + w4.z * w4.z + w4.w * w4.w;
#pragma unroll
        for (int o = 16; o; o >>= 1) v += __shfl_down_sync(0xffffffffu, v, o);
        if (lane == 0) sh1[wid] = v;         // reuse sh1
        __syncthreads();
        if (t == 0) {
            float a = 0.f;
#pragma unroll
            for (int i = 0; i < 8; i++) a += sh1[i];
            s_wsq = a;
        }
        __syncthreads();
    }
    const float wsq = s_wsq;

    // warp `wid` folds batches wid*4 .. wid*4+3 (fixed order -> deterministic)
#pragma unroll
    for (int j = 0; j < 4; j++) {
        const int bb = wid * 4 + j;
        const int pb = bb * CHUNKS;
        float a1 = __ldcg(&g_p1[pb + lane])       + __ldcg(&g_p1[pb + lane + 32]) +
                   __ldcg(&g_p1[pb + lane + 64])  + __ldcg(&g_p1[pb + lane + 96]);
        float a2 = __ldcg(&g_p2[pb + lane])       + __ldcg(&g_p2[pb + lane + 32]) +
                   __ldcg(&g_p2[pb + lane + 64])  + __ldcg(&g_p2[pb + lane + 96]);
#pragma unroll
        for (int o = 16; o; o >>= 1) {
            a1 += __shfl_down_sync(0xffffffffu, a1, o);
            a2 += __shfl_down_sync(0xffffffffu, a2, o);
        }
        if (lane == 0) {
            const float h = (a1 - lp1ref[bb]) - (a2 - lp2ref[bb]);
            const float z = BETA_F * h;
            const float p = pref[bb];
            // stable softplus: softplus(x) = max(x,0) + log1p(exp(-|x|))
            const float lp = log1pf(expf(-fabsf(z)));
            const float sp_pos = fmaxf(z, 0.f) + lp;   // softplus(z)  = l2
            const float sp_neg = fmaxf(-z, 0.f) + lp;  // softplus(-z) = l1
            const float ind = p * sp_neg + (1.f - p) * sp_pos;
            const float sig = 1.f / (1.f + expf(-z));
            const float c = BETA_F * (sig - p);
            s_ind[bb] = ind;
            s_gns[bb] = 2.f * (float)SS * wsq * c * c;
        }
    }
    __syncthreads();
    if (wid == 0) {
        float i = s_ind[lane];
        float g = s_gns[lane];
#pragma unroll
        for (int o = 16; o; o >>= 1) {
            i += __shfl_down_sync(0xffffffffu, i, o);
            g += __shfl_down_sync(0xffffffffu, g, o);
        }
        if (lane == 0) {
            out[0] = i * (1.f / (float)BB) + RHO_F * sqrtf(g * (1.f / (float)BB));
            g_count = 0;                     // reset ticket for next graph replay
        }
    }
}

extern "C" void kernel_launch(void* const* d_in, const int* in_sizes, int n_in,
                              void* d_out, int out_size) {
    const float* e1     = (const float*)d_in[0];  // emb_a1 (B,S,D)
    const float* e2     = (const float*)d_in[1];  // emb_a2 (B,S,D)
    const float* w      = (const float*)d_in[2];  // w (D,)
    const float* lp1ref = (const float*)d_in[3];  // log_prob_a1_ref (B,)
    const float* lp2ref = (const float*)d_in[4];  // log_prob_a2_ref (B,)
    const float* pref   = (const float*)d_in[5];  // preference (B,)
    float* out          = (float*)d_out;

    wdpo_fused<<<NBLK, 256>>>(e1, e2, w, lp1ref, lp2ref, pref, out);
}

// round 7
// speedup vs baseline: 1.0812x; 1.0492x over previous
#include <cuda_runtime.h>
#include <math.h>

#define BB 32
#define SS 2048
#define DD 1024
#define ROWS 16
#define CHUNKS (SS / ROWS)      // 128 blocks per batch
#define NBLK (BB * CHUNKS)      // 4096 blocks total
#define BETA_F 0.1f
#define RHO_F 1.0f

// Deterministic per-block partials (no float atomics -> bitwise stable across replays)
__device__ float g_p1[NBLK];
__device__ float g_p2[NBLK];

// ---------------- hot streaming kernel: R3 body, byte-identical ----------------
__global__ void __launch_bounds__(256) wdpo_reduce(const float* __restrict__ e1,
                                                   const float* __restrict__ e2,
                                                   const float* __restrict__ w) {
    const int t   = threadIdx.x;            // 0..255, owns float4 column group
    const int blk = blockIdx.x;
    const int b     = blk >> 7;             // / CHUNKS
    const int chunk = blk & (CHUNKS - 1);

    // each thread keeps its 4 w values in registers for the whole block
    const float4 w4 = reinterpret_cast<const float4*>(w)[t];

    const size_t base = ((size_t)b * SS + (size_t)chunk * ROWS) * DD + 4 * (size_t)t;
    const float4* __restrict__ p1 = reinterpret_cast<const float4*>(e1 + base);
    const float4* __restrict__ p2 = reinterpret_cast<const float4*>(e2 + base);

    float s1 = 0.f, s2 = 0.f;
#pragma unroll 8
    for (int r = 0; r < ROWS; r++) {
        const float4 a = p1[(size_t)r * (DD / 4)];
        const float4 c = p2[(size_t)r * (DD / 4)];
        s1 += a.x * w4.x + a.y * w4.y + a.z * w4.z + a.w * w4.w;
        s2 += c.x * w4.x + c.y * w4.y + c.z * w4.z + c.w * w4.w;
    }

    // block reduction: warp shuffle then 8-warp shared fold
    __shared__ float sh1[8], sh2[8];
#pragma unroll
    for (int o = 16; o; o >>= 1) {
        s1 += __shfl_down_sync(0xffffffffu, s1, o);
        s2 += __shfl_down_sync(0xffffffffu, s2, o);
    }
    const int lane = t & 31, wid = t >> 5;
    if (lane == 0) { sh1[wid] = s1; sh2[wid] = s2; }
    __syncthreads();
    if (wid == 0) {
        s1 = (lane < 8) ? sh1[lane] : 0.f;
        s2 = (lane < 8) ? sh2[lane] : 0.f;
#pragma unroll
        for (int o = 4; o; o >>= 1) {
            s1 += __shfl_down_sync(0xffffffffu, s1, o);
            s2 += __shfl_down_sync(0xffffffffu, s2, o);
        }
        if (lane == 0) { g_p1[blk] = s1; g_p2[blk] = s2; }
    }

    // PDL: this CTA's contribution is committed; let the dependent epilogue
    // grid begin launching while remaining CTAs drain.
    cudaTriggerProgrammaticLaunchCompletion();
}

// ---------------- epilogue: primary-independent work BEFORE the dependency ----
__global__ void __launch_bounds__(1024) wdpo_epilogue(const float* __restrict__ w,
                                                      const float* __restrict__ lp1ref,
                                                      const float* __restrict__ lp2ref,
                                                      const float* __restrict__ pref,
                                                      float* __restrict__ out) {
    const int t = threadIdx.x;
    const int lane = t & 31, wid = t >> 5;

    __shared__ float swsq[32];
    __shared__ float s_ind[32];
    __shared__ float s_gns[32];

    // ||w||^2 — reads only the kernel INPUT w, safe before the primary grid
    // finishes; overlaps with the reduce tail under PDL.
    float v = w[t];
    v = v * v;
#pragma unroll
    for (int o = 16; o; o >>= 1) v += __shfl_down_sync(0xffffffffu, v, o);
    if (lane == 0) swsq[wid] = v;
    __syncthreads();
    if (t == 0) {
        float a = 0.f;
#pragma unroll
        for (int i = 0; i < 32; i++) a += swsq[i];
        swsq[0] = a;
    }
    __syncthreads();
    const float wsq = swsq[0];

    // Wait for the primary grid (all partials written & visible).
    cudaGridDependencySynchronize();

    // warp `wid` folds the 128 partials of batch b = wid (deterministic order)
    const int b = wid;
    const int base = b * CHUNKS;
    float s1 = g_p1[base + lane] + g_p1[base + lane + 32] +
               g_p1[base + lane + 64] + g_p1[base + lane + 96];
    float s2 = g_p2[base + lane] + g_p2[base + lane + 32] +
               g_p2[base + lane + 64] + g_p2[base + lane + 96];
#pragma unroll
    for (int o = 16; o; o >>= 1) {
        s1 += __shfl_down_sync(0xffffffffu, s1, o);
        s2 += __shfl_down_sync(0xffffffffu, s2, o);
    }
    if (lane == 0) {
        const float h = (s1 - lp1ref[b]) - (s2 - lp2ref[b]);
        const float z = BETA_F * h;
        const float p = pref[b];
        // stable softplus: softplus(x) = max(x,0) + log1p(exp(-|x|))
        const float lp = log1pf(expf(-fabsf(z)));
        const float sp_pos = fmaxf(z, 0.f) + lp;   // softplus(z)  = l2
        const float sp_neg = fmaxf(-z, 0.f) + lp;  // softplus(-z) = l1
        const float ind = p * sp_neg + (1.f - p) * sp_pos;
        const float sig = 1.f / (1.f + expf(-z));
        const float c = BETA_F * (sig - p);
        s_ind[b] = ind;
        s_gns[b] = 2.f * (float)SS * wsq * c * c;
    }
    __syncthreads();
    if (wid == 0) {
        float i = s_ind[lane];
        float g = s_gns[lane];
#pragma unroll
        for (int o = 16; o; o >>= 1) {
            i += __shfl_down_sync(0xffffffffu, i, o);
            g += __shfl_down_sync(0xffffffffu, g, o);
        }
        if (lane == 0) out[0] = i * (1.f / (float)BB) + RHO_F * sqrtf(g * (1.f / (float)BB));
    }
}

extern "C" void kernel_launch(void* const* d_in, const int* in_sizes, int n_in,
                              void* d_out, int out_size) {
    const float* e1     = (const float*)d_in[0];  // emb_a1 (B,S,D)
    const float* e2     = (const float*)d_in[1];  // emb_a2 (B,S,D)
    const float* w      = (const float*)d_in[2];  // w (D,)
    const float* lp1ref = (const float*)d_in[3];  // log_prob_a1_ref (B,)
    const float* lp2ref = (const float*)d_in[4];  // log_prob_a2_ref (B,)
    const float* pref   = (const float*)d_in[5];  // preference (B,)
    float* out          = (float*)d_out;

    wdpo_reduce<<<NBLK, 256>>>(e1, e2, w);

    // Epilogue with programmatic dependent launch: overlaps its launch + wsq
    // phase with the reduce tail. If PDL is unsupported under capture this
    // degrades to an ordinary stream dependency (== R3 behavior).
    cudaLaunchConfig_t cfg = {};
    cfg.gridDim  = dim3(1, 1, 1);
    cfg.blockDim = dim3(1024, 1, 1);
    cfg.dynamicSmemBytes = 0;
    cfg.stream = 0;
    cudaLaunchAttribute attr[1];
    attr[0].id = cudaLaunchAttributeProgrammaticStreamSerialization;
    attr[0].val.programmaticStreamSerializationAllowed = 1;
    cfg.attrs = attr;
    cfg.numAttrs = 1;
    cudaError_t err = cudaLaunchKernelEx(&cfg, wdpo_epilogue, w, lp1ref, lp2ref, pref, out);
    if (err != cudaSuccess) {
        // Fallback: plain launch (identical semantics, no overlap)
        wdpo_epilogue<<<1, 1024>>>(w, lp1ref, lp2ref, pref, out);
    }
}